// round 10
// baseline (speedup 1.0000x reference)
#include <cuda_runtime.h>
#include <math.h>

// Problem constants
#define B_   2
#define S_   2048
#define E_   2048
#define HQ_  32
#define HKV_ 8
#define D_   64
#define KVD_ 512

// Scratch (static device arrays: allocation-free rule)
__device__ float  g_Q[(size_t)B_*S_*E_];       // 33.5 MB
__device__ float  g_K[(size_t)B_*S_*KVD_];     //  8.4 MB
__device__ float  g_V[(size_t)B_*S_*KVD_];     //  8.4 MB
__device__ float  g_C[(size_t)B_*S_*E_];       // 33.5 MB (context, pre-Wo)
__device__ float2 g_Stats[(size_t)64*2048];    //  1 MB  per-row (max, 1/sum)

// ---------------------------------------------------------------------------
// TF32 helpers
// ---------------------------------------------------------------------------
__device__ __forceinline__ unsigned f2tf(float f) {
    unsigned r;
    asm("cvt.rna.tf32.f32 %0, %1;" : "=r"(r) : "f"(f));
    return r;
}

__device__ __forceinline__ void mma_tf32(float c[4],
                                         unsigned a0, unsigned a1, unsigned a2, unsigned a3,
                                         unsigned b0, unsigned b1) {
    asm volatile(
        "mma.sync.aligned.m16n8k8.row.col.f32.tf32.tf32.f32 "
        "{%0,%1,%2,%3},{%4,%5,%6,%7},{%8,%9},{%0,%1,%2,%3};"
        : "+f"(c[0]), "+f"(c[1]), "+f"(c[2]), "+f"(c[3])
        : "r"(a0), "r"(a1), "r"(a2), "r"(a3), "r"(b0), "r"(b1));
}

__device__ __forceinline__ unsigned smem_u32(const void* p) {
    return (unsigned)__cvta_generic_to_shared(p);
}

__device__ __forceinline__ void cpasync16(unsigned dst, const void* src) {
    asm volatile("cp.async.ca.shared.global [%0], [%1], 16;\n" :: "r"(dst), "l"(src));
}

// ---------------------------------------------------------------------------
// Projection GEMM v3: C = A @ B + bias. 128x128x16 tiles, cp.async
// double-buffered raw-f32 stages, tf32 convert at fragment load.
//   A stage: 128 rows x pitch 20  (banks: 20*lr+lq -> all 32 distinct)
//   B stage: 16 rows  x pitch 136 (banks: 8*lq+lr  -> all 32 distinct)
// ---------------------------------------------------------------------------
#define APITCH 20
#define BPITCH 136

__global__ void __launch_bounds__(256, 2) mm_v3(
    int M, int N, int K,
    const float* __restrict__ A, int lda,
    const float* __restrict__ Bm, int ldb,
    float* __restrict__ C, int ldc,
    const float* __restrict__ bias)
{
    __shared__ __align__(16) float sA[2][128 * APITCH];
    __shared__ __align__(16) float sB[2][16 * BPITCH];

    const int t    = threadIdx.x;
    const int w    = t >> 5;
    const int lane = t & 31;
    const int lq   = lane & 3;
    const int lr   = lane >> 2;
    const int wm   = w & 1;
    const int wn   = w >> 1;
    const int m0   = blockIdx.y * 128;
    const int n0   = blockIdx.x * 128;

    auto prefetch = [&](int k0, int buf) {
        #pragma unroll
        for (int i = 0; i < 2; ++i) {
            int idx = t + i * 256;
            int m = idx >> 2, c4 = idx & 3;
            cpasync16(smem_u32(&sA[buf][m * APITCH + c4 * 4]),
                      A + (size_t)(m0 + m) * lda + k0 + c4 * 4);
        }
        #pragma unroll
        for (int i = 0; i < 2; ++i) {
            int idx = t + i * 256;
            int k = idx >> 5, c4 = idx & 31;
            cpasync16(smem_u32(&sB[buf][k * BPITCH + c4 * 4]),
                      Bm + (size_t)(k0 + k) * ldb + n0 + c4 * 4);
        }
        asm volatile("cp.async.commit_group;\n");
    };

    float acc[4][4][4];
    #pragma unroll
    for (int i = 0; i < 4; ++i)
        #pragma unroll
        for (int j = 0; j < 4; ++j)
            #pragma unroll
            for (int r = 0; r < 4; ++r) acc[i][j][r] = 0.f;

    const int NT = K / 16;
    prefetch(0, 0);

    for (int kt = 0; kt < NT; ++kt) {
        if (kt + 1 < NT) {
            prefetch((kt + 1) * 16, (kt + 1) & 1);
            asm volatile("cp.async.wait_group 1;\n");
        } else {
            asm volatile("cp.async.wait_group 0;\n");
        }
        __syncthreads();

        const float* pA = sA[kt & 1];
        const float* pB = sB[kt & 1];

        #pragma unroll
        for (int ks = 0; ks < 2; ++ks) {
            const int kk  = ks * 8 + lq;
            const int kkh = kk + 4;
            unsigned af[4][4], bf[4][2];
            #pragma unroll
            for (int mi = 0; mi < 4; ++mi) {
                int r = wm * 64 + mi * 16 + lr;
                af[mi][0] = f2tf(pA[ r      * APITCH + kk ]);
                af[mi][1] = f2tf(pA[(r + 8) * APITCH + kk ]);
                af[mi][2] = f2tf(pA[ r      * APITCH + kkh]);
                af[mi][3] = f2tf(pA[(r + 8) * APITCH + kkh]);
            }
            #pragma unroll
            for (int ni = 0; ni < 4; ++ni) {
                int n = wn * 32 + ni * 8 + lr;
                bf[ni][0] = f2tf(pB[kk  * BPITCH + n]);
                bf[ni][1] = f2tf(pB[kkh * BPITCH + n]);
            }
            #pragma unroll
            for (int mi = 0; mi < 4; ++mi)
                #pragma unroll
                for (int ni = 0; ni < 4; ++ni)
                    mma_tf32(acc[mi][ni], af[mi][0], af[mi][1], af[mi][2], af[mi][3],
                             bf[ni][0], bf[ni][1]);
        }
        __syncthreads();
    }

    #pragma unroll
    for (int mi = 0; mi < 4; ++mi) {
        int r0 = m0 + wm * 64 + mi * 16 + lr;
        int r1 = r0 + 8;
        #pragma unroll
        for (int ni = 0; ni < 4; ++ni) {
            int cc = n0 + wn * 32 + ni * 8 + 2 * lq;
            float b0 = bias[cc], b1 = bias[cc + 1];
            float2 v0 = { acc[mi][ni][0] + b0, acc[mi][ni][1] + b1 };
            float2 v1 = { acc[mi][ni][2] + b0, acc[mi][ni][3] + b1 };
            *(float2*)(C + (size_t)r0 * ldc + cc) = v0;
            *(float2*)(C + (size_t)r1 * ldc + cc) = v1;
        }
    }
}

// ---------------------------------------------------------------------------
// Scores kernel (R6, proven): persistent Q, cp.async double-buffered K.
// Writes raw S to attn buffer + final per-row (max, 1/sum) to g_Stats.
// ---------------------------------------------------------------------------
#define KPITCH 68
#define SC2_SMEM_BYTES (8192*4 + 2*128*KPITCH*4 + 4*128*8)

__global__ void __launch_bounds__(256, 2) scores_v2(
    const float* __restrict__ Q, const float* __restrict__ K,
    float* __restrict__ attn, float2* __restrict__ stats)
{
    extern __shared__ unsigned smu[];
    unsigned* sQ   = smu;                        // 64x128 tf32 (k-major swz)
    float*    sKf  = (float*)(sQ + 8192);        // 2 x 128 x 68 raw f32
    float2*   sRed = (float2*)(sKf + 2 * 128 * KPITCH);

    const int t    = threadIdx.x;
    const int w    = t >> 5;
    const int lane = t & 31;
    const int lq   = lane & 3;
    const int lr   = lane >> 2;
    const unsigned sw = lq << 3;
    const int wm = w & 1;
    const int wn = w >> 1;

    const int mt = blockIdx.x;
    const int bh = blockIdx.y;
    const int b  = bh >> 5;
    const int h  = bh & 31;
    const int hkv = h >> 2;

    const float* Qg = Q + ((size_t)b * S_ + mt * 128) * E_ + h * D_;
    const float* Kg = K + (size_t)b * S_ * KVD_ + hkv * D_;
    float* aRow = attn + (size_t)bh * S_ * S_ + (size_t)(mt * 128) * S_;

    #pragma unroll
    for (int i = 0; i < 8; ++i) {
        int idx = t + i * 256;
        int m = idx >> 4, q4 = idx & 15;
        float4 v = *(const float4*)(Qg + (size_t)m * E_ + q4 * 4);
        int kb = q4 * 4;
        sQ[(kb + 0) * 128 + (m ^ 0 )] = f2tf(0.125f * v.x);
        sQ[(kb + 1) * 128 + (m ^ 8 )] = f2tf(0.125f * v.y);
        sQ[(kb + 2) * 128 + (m ^ 16)] = f2tf(0.125f * v.z);
        sQ[(kb + 3) * 128 + (m ^ 24)] = f2tf(0.125f * v.w);
    }

    auto prefetchK = [&](int nt, int buf) {
        unsigned base = smem_u32(sKf + buf * 128 * KPITCH);
        const float* src = Kg + (size_t)(nt * 128) * KVD_;
        #pragma unroll
        for (int i = 0; i < 8; ++i) {
            int idx = t + i * 256;
            int n = idx >> 4, c = idx & 15;
            cpasync16(base + (unsigned)(n * KPITCH + c * 4) * 4u,
                      src + (size_t)n * KVD_ + c * 4);
        }
        asm volatile("cp.async.commit_group;\n");
    };

    float mrun[4][2], lrun[4][2];
    #pragma unroll
    for (int mi = 0; mi < 4; ++mi)
        #pragma unroll
        for (int rg = 0; rg < 2; ++rg) { mrun[mi][rg] = -1e30f; lrun[mi][rg] = 0.f; }

    prefetchK(0, 0);

    for (int nt = 0; nt < 16; ++nt) {
        if (nt < 15) {
            prefetchK(nt + 1, (nt + 1) & 1);
            asm volatile("cp.async.wait_group 1;\n");
        } else {
            asm volatile("cp.async.wait_group 0;\n");
        }
        __syncthreads();

        const float* sK = sKf + (nt & 1) * 128 * KPITCH;

        float acc[4][4][4];
        #pragma unroll
        for (int i = 0; i < 4; ++i)
            #pragma unroll
            for (int j = 0; j < 4; ++j)
                #pragma unroll
                for (int r = 0; r < 4; ++r) acc[i][j][r] = 0.f;

        #pragma unroll
        for (int ks = 0; ks < 8; ++ks) {
            const int kk  = ks * 8 + lq;
            const int kkh = kk + 4;
            unsigned a[4][4], bf[4][2];
            #pragma unroll
            for (int mi = 0; mi < 4; ++mi) {
                int r = wm * 64 + mi * 16 + lr;
                a[mi][0] = sQ[kk  * 128 + ( r      ^ sw)];
                a[mi][1] = sQ[kk  * 128 + ((r + 8) ^ sw)];
                a[mi][2] = sQ[kkh * 128 + ( r      ^ sw)];
                a[mi][3] = sQ[kkh * 128 + ((r + 8) ^ sw)];
            }
            #pragma unroll
            for (int ni = 0; ni < 4; ++ni) {
                int n = wn * 32 + ni * 8 + lr;
                bf[ni][0] = f2tf(sK[n * KPITCH + kk ]);
                bf[ni][1] = f2tf(sK[n * KPITCH + kkh]);
            }
            #pragma unroll
            for (int mi = 0; mi < 4; ++mi)
                #pragma unroll
                for (int ni = 0; ni < 4; ++ni)
                    mma_tf32(acc[mi][ni], a[mi][0], a[mi][1], a[mi][2], a[mi][3],
                             bf[ni][0], bf[ni][1]);
        }

        #pragma unroll
        for (int mi = 0; mi < 4; ++mi)
            #pragma unroll
            for (int rg = 0; rg < 2; ++rg) {
                int row = wm * 64 + mi * 16 + lr + rg * 8;
                float m8 = -1e30f;
                #pragma unroll
                for (int ni = 0; ni < 4; ++ni)
                    m8 = fmaxf(m8, fmaxf(acc[mi][ni][rg * 2], acc[mi][ni][rg * 2 + 1]));
                float l8 = 0.f;
                #pragma unroll
                for (int ni = 0; ni < 4; ++ni) {
                    int cc = wn * 32 + ni * 8 + 2 * lq;
                    float v0 = acc[mi][ni][rg * 2];
                    float v1 = acc[mi][ni][rg * 2 + 1];
                    float2 sv = { v0, v1 };
                    *(float2*)(aRow + (size_t)row * S_ + nt * 128 + cc) = sv;
                    l8 += __expf(v0 - m8) + __expf(v1 - m8);
                }
                float mn = fmaxf(mrun[mi][rg], m8);
                lrun[mi][rg] = lrun[mi][rg] * __expf(mrun[mi][rg] - mn)
                             + l8 * __expf(m8 - mn);
                mrun[mi][rg] = mn;
            }
        __syncthreads();
    }

    #pragma unroll
    for (int mi = 0; mi < 4; ++mi)
        #pragma unroll
        for (int rg = 0; rg < 2; ++rg) {
            float m = mrun[mi][rg], l = lrun[mi][rg];
            #pragma unroll
            for (int o = 1; o <= 2; o <<= 1) {
                float mo = __shfl_xor_sync(0xffffffffu, m, o);
                float lo = __shfl_xor_sync(0xffffffffu, l, o);
                float mn = fmaxf(m, mo);
                l = l * __expf(m - mn) + lo * __expf(mo - mn);
                m = mn;
            }
            if (lq == 0) {
                int row = wm * 64 + mi * 16 + lr + rg * 8;
                sRed[wn * 128 + row] = make_float2(m, l);
            }
        }
    __syncthreads();

    if (t < 128) {
        float2 p = sRed[t];
        float m = p.x, l = p.y;
        #pragma unroll
        for (int wni = 1; wni < 4; ++wni) {
            float2 q = sRed[wni * 128 + t];
            float mn = fmaxf(m, q.x);
            l = l * __expf(m - mn) + q.y * __expf(q.x - mn);
            m = mn;
        }
        stats[(size_t)bh * 2048 + mt * 128 + t] = make_float2(m, 1.0f / l);
    }
}

// ---------------------------------------------------------------------------
// Fused softmax + PV (R6, proven): block = 128 q rows of one (b,h).
// ---------------------------------------------------------------------------
#define PV_SMEM_BYTES (128*132*4 + 128*64*4 + 128*8)

__global__ void __launch_bounds__(512) pv_softmax(
    const float* __restrict__ V, float* __restrict__ attn,
    const float2* __restrict__ stats, float* __restrict__ Ctx)
{
    extern __shared__ unsigned smu[];
    unsigned* sP = smu;                    // 128 x 132 (row-major P, tf32)
    unsigned* sV = sP + 128 * 132;         // 64-col k-major swizzled V
    float2* sStats = (float2*)(sV + 128 * 64);  // 128

    const int t    = threadIdx.x;
    const int w    = t >> 5;
    const int lane = t & 31;
    const int lq   = lane & 3;
    const int lr   = lane >> 2;
    const unsigned sw = lq << 3;
    const int wm2 = w & 3;
    const int wn2 = w >> 2;

    const int q0 = blockIdx.x * 128;
    const int h  = blockIdx.y;
    const int b  = blockIdx.z;
    const int hkv = h >> 2;
    const int bh  = b * HQ_ + h;

    const float* Vg = V + (size_t)b * S_ * KVD_ + hkv * D_;
    float* aBase = attn + ((size_t)bh * S_ + q0) * S_;
    float* Cg = Ctx + ((size_t)b * S_ + q0) * E_ + h * D_;

    if (t < 128) sStats[t] = stats[(size_t)bh * 2048 + q0 + t];
    __syncthreads();

    float accO[2][2][4];
    #pragma unroll
    for (int i = 0; i < 2; ++i)
        #pragma unroll
        for (int j = 0; j < 2; ++j)
            #pragma unroll
            for (int r = 0; r < 4; ++r) accO[i][j][r] = 0.f;

    for (int kt = 0; kt < S_ / 128; ++kt) {
        #pragma unroll
        for (int i = 0; i < 8; ++i) {
            int idx = t + i * 512;
            int row = idx >> 5, c4 = idx & 31;
            float4* pS = (float4*)(aBase + (size_t)row * S_ + kt * 128);
            float4 v = pS[c4];
            float2 st = sStats[row];
            float p0 = __expf(v.x - st.x) * st.y;
            float p1 = __expf(v.y - st.x) * st.y;
            float p2 = __expf(v.z - st.x) * st.y;
            float p3 = __expf(v.w - st.x) * st.y;
            float4 pv = { p0, p1, p2, p3 };
            pS[c4] = pv;
            uint4 tv = { f2tf(p0), f2tf(p1), f2tf(p2), f2tf(p3) };
            *(uint4*)(&sP[row * 132 + c4 * 4]) = tv;
        }
        const float* Vt = Vg + (size_t)kt * 128 * KVD_;
        #pragma unroll
        for (int i = 0; i < 4; ++i) {
            int idx = t + i * 512;
            int kv = idx >> 4, q4 = idx & 15;
            float4 v = *(const float4*)(Vt + (size_t)kv * KVD_ + q4 * 4);
            unsigned c = (kv & 3) << 3;
            unsigned* dst = &sV[kv * 64 + ((q4 * 4) ^ c)];
            dst[0] = f2tf(v.x); dst[1] = f2tf(v.y);
            dst[2] = f2tf(v.z); dst[3] = f2tf(v.w);
        }
        __syncthreads();

        #pragma unroll
        for (int ks = 0; ks < 16; ++ks) {
            const int kk  = ks * 8 + lq;
            const int kkh = kk + 4;
            unsigned a[2][4], bf[2][2];
            #pragma unroll
            for (int mi = 0; mi < 2; ++mi) {
                int r = wm2 * 32 + mi * 16 + lr;
                a[mi][0] = sP[ r      * 132 + kk ];
                a[mi][1] = sP[(r + 8) * 132 + kk ];
                a[mi][2] = sP[ r      * 132 + kkh];
                a[mi][3] = sP[(r + 8) * 132 + kkh];
            }
            #pragma unroll
            for (int ni = 0; ni < 2; ++ni) {
                int d = wn2 * 16 + ni * 8 + lr;
                bf[ni][0] = sV[kk  * 64 + (d ^ sw)];
                bf[ni][1] = sV[kkh * 64 + (d ^ sw)];
            }
            #pragma unroll
            for (int mi = 0; mi < 2; ++mi)
                #pragma unroll
                for (int ni = 0; ni < 2; ++ni)
                    mma_tf32(accO[mi][ni], a[mi][0], a[mi][1], a[mi][2], a[mi][3],
                             bf[ni][0], bf[ni][1]);
        }
        __syncthreads();
    }

    #pragma unroll
    for (int mi = 0; mi < 2; ++mi)
        #pragma unroll
        for (int rg = 0; rg < 2; ++rg) {
            int row = wm2 * 32 + mi * 16 + lr + rg * 8;
            #pragma unroll
            for (int ni = 0; ni < 2; ++ni) {
                int d = wn2 * 16 + ni * 8 + 2 * lq;
                float2 v = { accO[mi][ni][rg * 2], accO[mi][ni][rg * 2 + 1] };
                *(float2*)(Cg + (size_t)row * E_ + d) = v;
            }
        }
}

// ---------------------------------------------------------------------------
extern "C" void kernel_launch(void* const* d_in, const int* in_sizes, int n_in,
                              void* d_out, int out_size)
{
    const float* query = (const float*)d_in[0];
    const float* key   = (const float*)d_in[1];
    const float* value = (const float*)d_in[2];
    const float* Wq = (const float*)d_in[3];
    const float* bq = (const float*)d_in[4];
    const float* Wk = (const float*)d_in[5];
    const float* bk = (const float*)d_in[6];
    const float* Wv = (const float*)d_in[7];
    const float* bv = (const float*)d_in[8];
    const float* Wo = (const float*)d_in[9];
    const float* bo = (const float*)d_in[10];
    float* out = (float*)d_out;

    float *qbuf, *kbuf, *vbuf, *cbuf;
    float2 *sbuf;
    cudaGetSymbolAddress((void**)&qbuf, g_Q);
    cudaGetSymbolAddress((void**)&kbuf, g_K);
    cudaGetSymbolAddress((void**)&vbuf, g_V);
    cudaGetSymbolAddress((void**)&cbuf, g_C);
    cudaGetSymbolAddress((void**)&sbuf, g_Stats);

    const int M = B_ * S_;                        // 4096
    float* attn = out + (size_t)B_ * S_ * E_;     // attn-weights output region

    // Projections (cp.async double-buffered TF32 GEMM — the kernel under test)
    mm_v3<<<dim3(E_/128,  M/128), 256>>>(M, E_,   E_, query, E_, Wq, E_,   qbuf, E_,   bq);
    mm_v3<<<dim3(KVD_/128, M/128), 256>>>(M, KVD_, E_, key,   E_, Wk, KVD_, kbuf, KVD_, bk);
    mm_v3<<<dim3(KVD_/128, M/128), 256>>>(M, KVD_, E_, value, E_, Wv, KVD_, vbuf, KVD_, bv);

    // Scores + exact row stats (R6 proven path)
    cudaFuncSetAttribute(scores_v2, cudaFuncAttributeMaxDynamicSharedMemorySize,
                         SC2_SMEM_BYTES);
    scores_v2<<<dim3(16, 64), 256, SC2_SMEM_BYTES>>>(qbuf, kbuf, attn, sbuf);

    // Softmax + attn write + PV (R6 proven path)
    cudaFuncSetAttribute(pv_softmax, cudaFuncAttributeMaxDynamicSharedMemorySize,
                         PV_SMEM_BYTES);
    pv_softmax<<<dim3(S_/128, HQ_, B_), 512, PV_SMEM_BYTES>>>(vbuf, attn, sbuf, cbuf);

    // Output projection
    mm_v3<<<dim3(E_/128, M/128), 256>>>(M, E_, E_, cbuf, E_, Wo, E_, out, E_, bo);
}

// round 14
// speedup vs baseline: 1.3200x; 1.3200x over previous
#include <cuda_runtime.h>
#include <math.h>

// Problem constants
#define B_   2
#define S_   2048
#define E_   2048
#define HQ_  32
#define HKV_ 8
#define D_   64
#define KVD_ 512

// Scratch (static device arrays: allocation-free rule)
__device__ float  g_Q[(size_t)B_*S_*E_];       // 33.5 MB
__device__ float  g_K[(size_t)B_*S_*KVD_];     //  8.4 MB
__device__ float  g_V[(size_t)B_*S_*KVD_];     //  8.4 MB
__device__ float  g_C[(size_t)B_*S_*E_];       // 33.5 MB (context, pre-Wo)
__device__ float2 g_Stats[(size_t)64*2048];    //  1 MB  per-row (max, 1/sum)

// ---------------------------------------------------------------------------
// TF32 helpers
// ---------------------------------------------------------------------------
__device__ __forceinline__ unsigned f2tf(float f) {
    unsigned r;
    asm("cvt.rna.tf32.f32 %0, %1;" : "=r"(r) : "f"(f));
    return r;
}

__device__ __forceinline__ void mma_tf32(float c[4],
                                         unsigned a0, unsigned a1, unsigned a2, unsigned a3,
                                         unsigned b0, unsigned b1) {
    asm volatile(
        "mma.sync.aligned.m16n8k8.row.col.f32.tf32.tf32.f32 "
        "{%0,%1,%2,%3},{%4,%5,%6,%7},{%8,%9},{%0,%1,%2,%3};"
        : "+f"(c[0]), "+f"(c[1]), "+f"(c[2]), "+f"(c[3])
        : "r"(a0), "r"(a1), "r"(a2), "r"(a3), "r"(b0), "r"(b1));
}

__device__ __forceinline__ unsigned smem_u32(const void* p) {
    return (unsigned)__cvta_generic_to_shared(p);
}

__device__ __forceinline__ void cpasync16(unsigned dst, const void* src) {
    asm volatile("cp.async.ca.shared.global [%0], [%1], 16;\n" :: "r"(dst), "l"(src));
}

// ---------------------------------------------------------------------------
// Projection TF32 GEMM (R3/R6 proven): C = A @ B + bias
// ---------------------------------------------------------------------------
#define BKK 16

template<int BM, int BN>
__global__ void __launch_bounds__((BM/64)*(BN/32)*32) mm_tf32(
    int M, int N, int K,
    const float* __restrict__ A, int lda,
    const float* __restrict__ Bm, int ldb,
    float* __restrict__ C, int ldc,
    const float* __restrict__ bias)
{
    constexpr int WM_ = BM / 64;
    constexpr int WN_ = BN / 32;
    constexpr int NTH = WM_ * WN_ * 32;

    __shared__ unsigned As[BKK * BM];
    __shared__ unsigned Bs[BKK * BN];

    const int t    = threadIdx.x;
    const int w    = t >> 5;
    const int lane = t & 31;
    const int wm   = w % WM_;
    const int wn   = w / WM_;
    const int m0   = blockIdx.y * BM;
    const int n0   = blockIdx.x * BN;

    float acc[4][4][4];
    #pragma unroll
    for (int i = 0; i < 4; ++i)
        #pragma unroll
        for (int j = 0; j < 4; ++j)
            #pragma unroll
            for (int r = 0; r < 4; ++r) acc[i][j][r] = 0.f;

    const unsigned sw = (lane & 3) << 3;

    for (int k0 = 0; k0 < K; k0 += BKK) {
        #pragma unroll
        for (int idx = t; idx < BM * BKK / 4; idx += NTH) {
            int quad = idx & 3;
            int m    = idx >> 2;
            float4 v = *(const float4*)(A + (size_t)(m0 + m) * lda + k0 + quad * 4);
            int kb = quad * 4;
            As[(kb + 0) * BM + (m ^ 0 )] = f2tf(v.x);
            As[(kb + 1) * BM + (m ^ 8 )] = f2tf(v.y);
            As[(kb + 2) * BM + (m ^ 16)] = f2tf(v.z);
            As[(kb + 3) * BM + (m ^ 24)] = f2tf(v.w);
        }
        #pragma unroll
        for (int idx = t; idx < BKK * BN / 4; idx += NTH) {
            int nq = idx % (BN / 4);
            int k  = idx / (BN / 4);
            float4 v = *(const float4*)(Bm + (size_t)(k0 + k) * ldb + n0 + nq * 4);
            unsigned c = (k & 3) << 3;
            unsigned* dst = &Bs[k * BN + ((nq * 4) ^ c)];
            dst[0] = f2tf(v.x); dst[1] = f2tf(v.y);
            dst[2] = f2tf(v.z); dst[3] = f2tf(v.w);
        }
        __syncthreads();

        #pragma unroll
        for (int ks = 0; ks < BKK / 8; ++ks) {
            const int kk  = ks * 8 + (lane & 3);
            const int kk2 = kk + 4;

            unsigned af[4][4];
            #pragma unroll
            for (int mi = 0; mi < 4; ++mi) {
                int r = wm * 64 + mi * 16 + (lane >> 2);
                af[mi][0] = As[kk  * BM + ( r      ^ sw)];
                af[mi][1] = As[kk  * BM + ((r + 8) ^ sw)];
                af[mi][2] = As[kk2 * BM + ( r      ^ sw)];
                af[mi][3] = As[kk2 * BM + ((r + 8) ^ sw)];
            }
            unsigned bf[4][2];
            #pragma unroll
            for (int ni = 0; ni < 4; ++ni) {
                int n = wn * 32 + ni * 8 + (lane >> 2);
                bf[ni][0] = Bs[kk  * BN + (n ^ sw)];
                bf[ni][1] = Bs[kk2 * BN + (n ^ sw)];
            }
            #pragma unroll
            for (int mi = 0; mi < 4; ++mi)
                #pragma unroll
                for (int ni = 0; ni < 4; ++ni)
                    mma_tf32(acc[mi][ni], af[mi][0], af[mi][1], af[mi][2], af[mi][3],
                             bf[ni][0], bf[ni][1]);
        }
        __syncthreads();
    }

    #pragma unroll
    for (int mi = 0; mi < 4; ++mi) {
        int r0 = m0 + wm * 64 + mi * 16 + (lane >> 2);
        int r1 = r0 + 8;
        #pragma unroll
        for (int ni = 0; ni < 4; ++ni) {
            int cc = n0 + wn * 32 + ni * 8 + 2 * (lane & 3);
            float b0 = bias[cc], b1 = bias[cc + 1];
            float2 v0 = { acc[mi][ni][0] + b0, acc[mi][ni][1] + b1 };
            float2 v1 = { acc[mi][ni][2] + b0, acc[mi][ni][3] + b1 };
            *(float2*)(C + (size_t)r0 * ldc + cc) = v0;
            *(float2*)(C + (size_t)r1 * ldc + cc) = v1;
        }
    }
}

// ---------------------------------------------------------------------------
// Scores kernel (R6, proven): persistent Q, cp.async double-buffered K.
// Writes raw S to attn buffer + final per-row (max, 1/sum) to g_Stats.
// ---------------------------------------------------------------------------
#define KPITCH 68
#define SC2_SMEM_BYTES (8192*4 + 2*128*KPITCH*4 + 4*128*8)

__global__ void __launch_bounds__(256, 2) scores_v2(
    const float* __restrict__ Q, const float* __restrict__ K,
    float* __restrict__ attn, float2* __restrict__ stats)
{
    extern __shared__ unsigned smu[];
    unsigned* sQ   = smu;                        // 64x128 tf32 (k-major swz)
    float*    sKf  = (float*)(sQ + 8192);        // 2 x 128 x 68 raw f32
    float2*   sRed = (float2*)(sKf + 2 * 128 * KPITCH);

    const int t    = threadIdx.x;
    const int w    = t >> 5;
    const int lane = t & 31;
    const int lq   = lane & 3;
    const int lr   = lane >> 2;
    const unsigned sw = lq << 3;
    const int wm = w & 1;
    const int wn = w >> 1;

    const int mt = blockIdx.x;
    const int bh = blockIdx.y;
    const int b  = bh >> 5;
    const int h  = bh & 31;
    const int hkv = h >> 2;

    const float* Qg = Q + ((size_t)b * S_ + mt * 128) * E_ + h * D_;
    const float* Kg = K + (size_t)b * S_ * KVD_ + hkv * D_;
    float* aRow = attn + (size_t)bh * S_ * S_ + (size_t)(mt * 128) * S_;

    #pragma unroll
    for (int i = 0; i < 8; ++i) {
        int idx = t + i * 256;
        int m = idx >> 4, q4 = idx & 15;
        float4 v = *(const float4*)(Qg + (size_t)m * E_ + q4 * 4);
        int kb = q4 * 4;
        sQ[(kb + 0) * 128 + (m ^ 0 )] = f2tf(0.125f * v.x);
        sQ[(kb + 1) * 128 + (m ^ 8 )] = f2tf(0.125f * v.y);
        sQ[(kb + 2) * 128 + (m ^ 16)] = f2tf(0.125f * v.z);
        sQ[(kb + 3) * 128 + (m ^ 24)] = f2tf(0.125f * v.w);
    }

    auto prefetchK = [&](int nt, int buf) {
        unsigned base = smem_u32(sKf + buf * 128 * KPITCH);
        const float* src = Kg + (size_t)(nt * 128) * KVD_;
        #pragma unroll
        for (int i = 0; i < 8; ++i) {
            int idx = t + i * 256;
            int n = idx >> 4, c = idx & 15;
            cpasync16(base + (unsigned)(n * KPITCH + c * 4) * 4u,
                      src + (size_t)n * KVD_ + c * 4);
        }
        asm volatile("cp.async.commit_group;\n");
    };

    float mrun[4][2], lrun[4][2];
    #pragma unroll
    for (int mi = 0; mi < 4; ++mi)
        #pragma unroll
        for (int rg = 0; rg < 2; ++rg) { mrun[mi][rg] = -1e30f; lrun[mi][rg] = 0.f; }

    prefetchK(0, 0);

    for (int nt = 0; nt < 16; ++nt) {
        if (nt < 15) {
            prefetchK(nt + 1, (nt + 1) & 1);
            asm volatile("cp.async.wait_group 1;\n");
        } else {
            asm volatile("cp.async.wait_group 0;\n");
        }
        __syncthreads();

        const float* sK = sKf + (nt & 1) * 128 * KPITCH;

        float acc[4][4][4];
        #pragma unroll
        for (int i = 0; i < 4; ++i)
            #pragma unroll
            for (int j = 0; j < 4; ++j)
                #pragma unroll
                for (int r = 0; r < 4; ++r) acc[i][j][r] = 0.f;

        #pragma unroll
        for (int ks = 0; ks < 8; ++ks) {
            const int kk  = ks * 8 + lq;
            const int kkh = kk + 4;
            unsigned a[4][4], bf[4][2];
            #pragma unroll
            for (int mi = 0; mi < 4; ++mi) {
                int r = wm * 64 + mi * 16 + lr;
                a[mi][0] = sQ[kk  * 128 + ( r      ^ sw)];
                a[mi][1] = sQ[kk  * 128 + ((r + 8) ^ sw)];
                a[mi][2] = sQ[kkh * 128 + ( r      ^ sw)];
                a[mi][3] = sQ[kkh * 128 + ((r + 8) ^ sw)];
            }
            #pragma unroll
            for (int ni = 0; ni < 4; ++ni) {
                int n = wn * 32 + ni * 8 + lr;
                bf[ni][0] = f2tf(sK[n * KPITCH + kk ]);
                bf[ni][1] = f2tf(sK[n * KPITCH + kkh]);
            }
            #pragma unroll
            for (int mi = 0; mi < 4; ++mi)
                #pragma unroll
                for (int ni = 0; ni < 4; ++ni)
                    mma_tf32(acc[mi][ni], a[mi][0], a[mi][1], a[mi][2], a[mi][3],
                             bf[ni][0], bf[ni][1]);
        }

        #pragma unroll
        for (int mi = 0; mi < 4; ++mi)
            #pragma unroll
            for (int rg = 0; rg < 2; ++rg) {
                int row = wm * 64 + mi * 16 + lr + rg * 8;
                float m8 = -1e30f;
                #pragma unroll
                for (int ni = 0; ni < 4; ++ni)
                    m8 = fmaxf(m8, fmaxf(acc[mi][ni][rg * 2], acc[mi][ni][rg * 2 + 1]));
                float l8 = 0.f;
                #pragma unroll
                for (int ni = 0; ni < 4; ++ni) {
                    int cc = wn * 32 + ni * 8 + 2 * lq;
                    float v0 = acc[mi][ni][rg * 2];
                    float v1 = acc[mi][ni][rg * 2 + 1];
                    float2 sv = { v0, v1 };
                    *(float2*)(aRow + (size_t)row * S_ + nt * 128 + cc) = sv;
                    l8 += __expf(v0 - m8) + __expf(v1 - m8);
                }
                float mn = fmaxf(mrun[mi][rg], m8);
                lrun[mi][rg] = lrun[mi][rg] * __expf(mrun[mi][rg] - mn)
                             + l8 * __expf(m8 - mn);
                mrun[mi][rg] = mn;
            }
        __syncthreads();
    }

    #pragma unroll
    for (int mi = 0; mi < 4; ++mi)
        #pragma unroll
        for (int rg = 0; rg < 2; ++rg) {
            float m = mrun[mi][rg], l = lrun[mi][rg];
            #pragma unroll
            for (int o = 1; o <= 2; o <<= 1) {
                float mo = __shfl_xor_sync(0xffffffffu, m, o);
                float lo = __shfl_xor_sync(0xffffffffu, l, o);
                float mn = fmaxf(m, mo);
                l = l * __expf(m - mn) + lo * __expf(mo - mn);
                m = mn;
            }
            if (lq == 0) {
                int row = wm * 64 + mi * 16 + lr + rg * 8;
                sRed[wn * 128 + row] = make_float2(m, l);
            }
        }
    __syncthreads();

    if (t < 128) {
        float2 p = sRed[t];
        float m = p.x, l = p.y;
        #pragma unroll
        for (int wni = 1; wni < 4; ++wni) {
            float2 q = sRed[wni * 128 + t];
            float mn = fmaxf(m, q.x);
            l = l * __expf(m - mn) + q.y * __expf(q.x - mn);
            m = mn;
        }
        stats[(size_t)bh * 2048 + mt * 128 + t] = make_float2(m, 1.0f / l);
    }
}

// ---------------------------------------------------------------------------
// Fused softmax + PV, v2: identical math/layout to R6's proven pv_softmax,
// plus register software-pipelining of the S-tile reads: tile kt+1's LDGs
// are issued right after tile kt's P is staged, so their latency hides under
// the PV mma phase instead of being exposed at the next iteration's start.
// ---------------------------------------------------------------------------
#define PV_SMEM_BYTES (128*132*4 + 128*64*4 + 128*8)

__global__ void __launch_bounds__(512) pv_softmax(
    const float* __restrict__ V, float* __restrict__ attn,
    const float2* __restrict__ stats, float* __restrict__ Ctx)
{
    extern __shared__ unsigned smu[];
    unsigned* sP = smu;                    // 128 x 132 (row-major P, tf32)
    unsigned* sV = sP + 128 * 132;         // 64-col k-major swizzled V
    float2* sStats = (float2*)(sV + 128 * 64);  // 128

    const int t    = threadIdx.x;
    const int w    = t >> 5;
    const int lane = t & 31;
    const int lq   = lane & 3;
    const int lr   = lane >> 2;
    const unsigned sw = lq << 3;
    const int wm2 = w & 3;
    const int wn2 = w >> 2;

    const int q0 = blockIdx.x * 128;
    const int h  = blockIdx.y;
    const int b  = blockIdx.z;
    const int hkv = h >> 2;
    const int bh  = b * HQ_ + h;

    const float* Vg = V + (size_t)b * S_ * KVD_ + hkv * D_;
    float* aBase = attn + ((size_t)bh * S_ + q0) * S_;
    float* Cg = Ctx + ((size_t)b * S_ + q0) * E_ + h * D_;

    if (t < 128) sStats[t] = stats[(size_t)bh * 2048 + q0 + t];

    // ---- S-tile register pipeline: preload tile 0 ----
    float4 vReg[8];
    #pragma unroll
    for (int i = 0; i < 8; ++i) {
        int idx = t + i * 512;
        int row = idx >> 5, c4 = idx & 31;
        vReg[i] = *(const float4*)(aBase + (size_t)row * S_ + c4 * 4);
    }
    __syncthreads();   // sStats visible

    float accO[2][2][4];
    #pragma unroll
    for (int i = 0; i < 2; ++i)
        #pragma unroll
        for (int j = 0; j < 2; ++j)
            #pragma unroll
            for (int r = 0; r < 4; ++r) accO[i][j][r] = 0.f;

    for (int kt = 0; kt < S_ / 128; ++kt) {
        // ---- stage V tile (proven swizzle) ----
        const float* Vt = Vg + (size_t)kt * 128 * KVD_;
        #pragma unroll
        for (int i = 0; i < 4; ++i) {
            int idx = t + i * 512;
            int kv = idx >> 4, q4 = idx & 15;
            float4 v = *(const float4*)(Vt + (size_t)kv * KVD_ + q4 * 4);
            unsigned c = (kv & 3) << 3;
            unsigned* dst = &sV[kv * 64 + ((q4 * 4) ^ c)];
            dst[0] = f2tf(v.x); dst[1] = f2tf(v.y);
            dst[2] = f2tf(v.z); dst[3] = f2tf(v.w);
        }

        // ---- P = exp(s-m)*inv from the pipelined regs: gmem write + sP stage ----
        #pragma unroll
        for (int i = 0; i < 8; ++i) {
            int idx = t + i * 512;
            int row = idx >> 5, c4 = idx & 31;
            float2 st = sStats[row];
            float4 v = vReg[i];
            float p0 = __expf(v.x - st.x) * st.y;
            float p1 = __expf(v.y - st.x) * st.y;
            float p2 = __expf(v.z - st.x) * st.y;
            float p3 = __expf(v.w - st.x) * st.y;
            float4 pv = { p0, p1, p2, p3 };
            *(float4*)(aBase + (size_t)row * S_ + kt * 128 + c4 * 4) = pv;
            uint4 tv = { f2tf(p0), f2tf(p1), f2tf(p2), f2tf(p3) };
            *(uint4*)(&sP[row * 132 + c4 * 4]) = tv;
        }

        // ---- issue next tile's S loads (latency hides under the mma phase) ----
        if (kt + 1 < S_ / 128) {
            #pragma unroll
            for (int i = 0; i < 8; ++i) {
                int idx = t + i * 512;
                int row = idx >> 5, c4 = idx & 31;
                vReg[i] = *(const float4*)(aBase + (size_t)row * S_
                                           + (kt + 1) * 128 + c4 * 4);
            }
        }
        __syncthreads();

        // ---- O += P @ V ----
        #pragma unroll
        for (int ks = 0; ks < 16; ++ks) {
            const int kk  = ks * 8 + lq;
            const int kkh = kk + 4;
            unsigned a[2][4], bf[2][2];
            #pragma unroll
            for (int mi = 0; mi < 2; ++mi) {
                int r = wm2 * 32 + mi * 16 + lr;
                a[mi][0] = sP[ r      * 132 + kk ];
                a[mi][1] = sP[(r + 8) * 132 + kk ];
                a[mi][2] = sP[ r      * 132 + kkh];
                a[mi][3] = sP[(r + 8) * 132 + kkh];
            }
            #pragma unroll
            for (int ni = 0; ni < 2; ++ni) {
                int d = wn2 * 16 + ni * 8 + lr;
                bf[ni][0] = sV[kk  * 64 + (d ^ sw)];
                bf[ni][1] = sV[kkh * 64 + (d ^ sw)];
            }
            #pragma unroll
            for (int mi = 0; mi < 2; ++mi)
                #pragma unroll
                for (int ni = 0; ni < 2; ++ni)
                    mma_tf32(accO[mi][ni], a[mi][0], a[mi][1], a[mi][2], a[mi][3],
                             bf[ni][0], bf[ni][1]);
        }
        __syncthreads();
    }

    #pragma unroll
    for (int mi = 0; mi < 2; ++mi)
        #pragma unroll
        for (int rg = 0; rg < 2; ++rg) {
            int row = wm2 * 32 + mi * 16 + lr + rg * 8;
            #pragma unroll
            for (int ni = 0; ni < 2; ++ni) {
                int d = wn2 * 16 + ni * 8 + 2 * lq;
                float2 v = { accO[mi][ni][rg * 2], accO[mi][ni][rg * 2 + 1] };
                *(float2*)(Cg + (size_t)row * E_ + d) = v;
            }
        }
}

// ---------------------------------------------------------------------------
extern "C" void kernel_launch(void* const* d_in, const int* in_sizes, int n_in,
                              void* d_out, int out_size)
{
    const float* query = (const float*)d_in[0];
    const float* key   = (const float*)d_in[1];
    const float* value = (const float*)d_in[2];
    const float* Wq = (const float*)d_in[3];
    const float* bq = (const float*)d_in[4];
    const float* Wk = (const float*)d_in[5];
    const float* bk = (const float*)d_in[6];
    const float* Wv = (const float*)d_in[7];
    const float* bv = (const float*)d_in[8];
    const float* Wo = (const float*)d_in[9];
    const float* bo = (const float*)d_in[10];
    float* out = (float*)d_out;

    float *qbuf, *kbuf, *vbuf, *cbuf;
    float2 *sbuf;
    cudaGetSymbolAddress((void**)&qbuf, g_Q);
    cudaGetSymbolAddress((void**)&kbuf, g_K);
    cudaGetSymbolAddress((void**)&vbuf, g_V);
    cudaGetSymbolAddress((void**)&cbuf, g_C);
    cudaGetSymbolAddress((void**)&sbuf, g_Stats);

    const int M = B_ * S_;                        // 4096
    float* attn = out + (size_t)B_ * S_ * E_;     // attn-weights output region

    // Projections (R6-proven mm_tf32)
    mm_tf32<128,128><<<dim3(E_/128,  M/128), 256>>>(
        M, E_,   E_, query, E_, Wq, E_,   qbuf, E_,   bq);
    mm_tf32<128,128><<<dim3(KVD_/128, M/128), 256>>>(
        M, KVD_, E_, key,   E_, Wk, KVD_, kbuf, KVD_, bk);
    mm_tf32<128,128><<<dim3(KVD_/128, M/128), 256>>>(
        M, KVD_, E_, value, E_, Wv, KVD_, vbuf, KVD_, bv);

    // Scores + exact row stats (R6 proven)
    cudaFuncSetAttribute(scores_v2, cudaFuncAttributeMaxDynamicSharedMemorySize,
                         SC2_SMEM_BYTES);
    scores_v2<<<dim3(16, 64), 256, SC2_SMEM_BYTES>>>(qbuf, kbuf, attn, sbuf);

    // Softmax + attn write + PV (register-pipelined S reads)
    cudaFuncSetAttribute(pv_softmax, cudaFuncAttributeMaxDynamicSharedMemorySize,
                         PV_SMEM_BYTES);
    pv_softmax<<<dim3(S_/128, HQ_, B_), 512, PV_SMEM_BYTES>>>(vbuf, attn, sbuf, cbuf);

    // Output projection
    mm_tf32<128,128><<<dim3(E_/128, M/128), 256>>>(
        M, E_, E_, cbuf, E_, Wo, E_, out, E_, bo);
}

// round 16
// speedup vs baseline: 1.5132x; 1.1464x over previous
#include <cuda_runtime.h>
#include <math.h>

// Problem constants
#define B_   2
#define S_   2048
#define E_   2048
#define HQ_  32
#define HKV_ 8
#define D_   64
#define KVD_ 512

// Scratch (static device arrays: allocation-free rule)
__device__ float  g_Q[(size_t)B_*S_*E_];       // 33.5 MB
__device__ float  g_K[(size_t)B_*S_*KVD_];     //  8.4 MB
__device__ float  g_V[(size_t)B_*S_*KVD_];     //  8.4 MB
__device__ float  g_C[(size_t)B_*S_*E_];       // 33.5 MB (context, pre-Wo)
__device__ float2 g_Stats[(size_t)64*2048];    //  1 MB  per-row (max, 1/sum)

// ---------------------------------------------------------------------------
// TF32 helpers
// ---------------------------------------------------------------------------
__device__ __forceinline__ unsigned f2tf(float f) {
    unsigned r;
    asm("cvt.rna.tf32.f32 %0, %1;" : "=r"(r) : "f"(f));
    return r;
}

__device__ __forceinline__ void mma_tf32(float c[4],
                                         unsigned a0, unsigned a1, unsigned a2, unsigned a3,
                                         unsigned b0, unsigned b1) {
    asm volatile(
        "mma.sync.aligned.m16n8k8.row.col.f32.tf32.tf32.f32 "
        "{%0,%1,%2,%3},{%4,%5,%6,%7},{%8,%9},{%0,%1,%2,%3};"
        : "+f"(c[0]), "+f"(c[1]), "+f"(c[2]), "+f"(c[3])
        : "r"(a0), "r"(a1), "r"(a2), "r"(a3), "r"(b0), "r"(b1));
}

__device__ __forceinline__ unsigned smem_u32(const void* p) {
    return (unsigned)__cvta_generic_to_shared(p);
}

__device__ __forceinline__ void cpasync16(unsigned dst, const void* src) {
    asm volatile("cp.async.ca.shared.global [%0], [%1], 16;\n" :: "r"(dst), "l"(src));
}

// ---------------------------------------------------------------------------
// Projection GEMM (R10-verified mm_v3): C = A @ B + bias. 128x128x16 tiles,
// cp.async double-buffered raw-f32 stages, tf32 convert at fragment load.
//   A stage: 128 rows x pitch 20  (banks: 20*lr+lq -> all 32 distinct)
//   B stage: 16 rows  x pitch 136 (banks: 8*lq+lr  -> all 32 distinct)
// ---------------------------------------------------------------------------
#define APITCH 20
#define BPITCH 136

__global__ void __launch_bounds__(256, 2) mm_v3(
    int M, int N, int K,
    const float* __restrict__ A, int lda,
    const float* __restrict__ Bm, int ldb,
    float* __restrict__ C, int ldc,
    const float* __restrict__ bias)
{
    __shared__ __align__(16) float sA[2][128 * APITCH];
    __shared__ __align__(16) float sB[2][16 * BPITCH];

    const int t    = threadIdx.x;
    const int w    = t >> 5;
    const int lane = t & 31;
    const int lq   = lane & 3;
    const int lr   = lane >> 2;
    const int wm   = w & 1;
    const int wn   = w >> 1;
    const int m0   = blockIdx.y * 128;
    const int n0   = blockIdx.x * 128;

    auto prefetch = [&](int k0, int buf) {
        #pragma unroll
        for (int i = 0; i < 2; ++i) {
            int idx = t + i * 256;
            int m = idx >> 2, c4 = idx & 3;
            cpasync16(smem_u32(&sA[buf][m * APITCH + c4 * 4]),
                      A + (size_t)(m0 + m) * lda + k0 + c4 * 4);
        }
        #pragma unroll
        for (int i = 0; i < 2; ++i) {
            int idx = t + i * 256;
            int k = idx >> 5, c4 = idx & 31;
            cpasync16(smem_u32(&sB[buf][k * BPITCH + c4 * 4]),
                      Bm + (size_t)(k0 + k) * ldb + n0 + c4 * 4);
        }
        asm volatile("cp.async.commit_group;\n");
    };

    float acc[4][4][4];
    #pragma unroll
    for (int i = 0; i < 4; ++i)
        #pragma unroll
        for (int j = 0; j < 4; ++j)
            #pragma unroll
            for (int r = 0; r < 4; ++r) acc[i][j][r] = 0.f;

    const int NT = K / 16;
    prefetch(0, 0);

    for (int kt = 0; kt < NT; ++kt) {
        if (kt + 1 < NT) {
            prefetch((kt + 1) * 16, (kt + 1) & 1);
            asm volatile("cp.async.wait_group 1;\n");
        } else {
            asm volatile("cp.async.wait_group 0;\n");
        }
        __syncthreads();

        const float* pA = sA[kt & 1];
        const float* pB = sB[kt & 1];

        #pragma unroll
        for (int ks = 0; ks < 2; ++ks) {
            const int kk  = ks * 8 + lq;
            const int kkh = kk + 4;
            unsigned af[4][4], bf[4][2];
            #pragma unroll
            for (int mi = 0; mi < 4; ++mi) {
                int r = wm * 64 + mi * 16 + lr;
                af[mi][0] = f2tf(pA[ r      * APITCH + kk ]);
                af[mi][1] = f2tf(pA[(r + 8) * APITCH + kk ]);
                af[mi][2] = f2tf(pA[ r      * APITCH + kkh]);
                af[mi][3] = f2tf(pA[(r + 8) * APITCH + kkh]);
            }
            #pragma unroll
            for (int ni = 0; ni < 4; ++ni) {
                int n = wn * 32 + ni * 8 + lr;
                bf[ni][0] = f2tf(pB[kk  * BPITCH + n]);
                bf[ni][1] = f2tf(pB[kkh * BPITCH + n]);
            }
            #pragma unroll
            for (int mi = 0; mi < 4; ++mi)
                #pragma unroll
                for (int ni = 0; ni < 4; ++ni)
                    mma_tf32(acc[mi][ni], af[mi][0], af[mi][1], af[mi][2], af[mi][3],
                             bf[ni][0], bf[ni][1]);
        }
        __syncthreads();
    }

    #pragma unroll
    for (int mi = 0; mi < 4; ++mi) {
        int r0 = m0 + wm * 64 + mi * 16 + lr;
        int r1 = r0 + 8;
        #pragma unroll
        for (int ni = 0; ni < 4; ++ni) {
            int cc = n0 + wn * 32 + ni * 8 + 2 * lq;
            float b0 = bias[cc], b1 = bias[cc + 1];
            float2 v0 = { acc[mi][ni][0] + b0, acc[mi][ni][1] + b1 };
            float2 v1 = { acc[mi][ni][2] + b0, acc[mi][ni][3] + b1 };
            *(float2*)(C + (size_t)r0 * ldc + cc) = v0;
            *(float2*)(C + (size_t)r1 * ldc + cc) = v1;
        }
    }
}

// ---------------------------------------------------------------------------
// Scores kernel (R6, proven): persistent Q, cp.async double-buffered K.
// Writes raw S to attn buffer + final per-row (max, 1/sum) to g_Stats.
// ALSO the clock canary: healthy runs measure this at ~380 us.
// ---------------------------------------------------------------------------
#define KPITCH 68
#define SC2_SMEM_BYTES (8192*4 + 2*128*KPITCH*4 + 4*128*8)

__global__ void __launch_bounds__(256, 2) scores_v2(
    const float* __restrict__ Q, const float* __restrict__ K,
    float* __restrict__ attn, float2* __restrict__ stats)
{
    extern __shared__ unsigned smu[];
    unsigned* sQ   = smu;                        // 64x128 tf32 (k-major swz)
    float*    sKf  = (float*)(sQ + 8192);        // 2 x 128 x 68 raw f32
    float2*   sRed = (float2*)(sKf + 2 * 128 * KPITCH);

    const int t    = threadIdx.x;
    const int w    = t >> 5;
    const int lane = t & 31;
    const int lq   = lane & 3;
    const int lr   = lane >> 2;
    const unsigned sw = lq << 3;
    const int wm = w & 1;
    const int wn = w >> 1;

    const int mt = blockIdx.x;
    const int bh = blockIdx.y;
    const int b  = bh >> 5;
    const int h  = bh & 31;
    const int hkv = h >> 2;

    const float* Qg = Q + ((size_t)b * S_ + mt * 128) * E_ + h * D_;
    const float* Kg = K + (size_t)b * S_ * KVD_ + hkv * D_;
    float* aRow = attn + (size_t)bh * S_ * S_ + (size_t)(mt * 128) * S_;

    #pragma unroll
    for (int i = 0; i < 8; ++i) {
        int idx = t + i * 256;
        int m = idx >> 4, q4 = idx & 15;
        float4 v = *(const float4*)(Qg + (size_t)m * E_ + q4 * 4);
        int kb = q4 * 4;
        sQ[(kb + 0) * 128 + (m ^ 0 )] = f2tf(0.125f * v.x);
        sQ[(kb + 1) * 128 + (m ^ 8 )] = f2tf(0.125f * v.y);
        sQ[(kb + 2) * 128 + (m ^ 16)] = f2tf(0.125f * v.z);
        sQ[(kb + 3) * 128 + (m ^ 24)] = f2tf(0.125f * v.w);
    }

    auto prefetchK = [&](int nt, int buf) {
        unsigned base = smem_u32(sKf + buf * 128 * KPITCH);
        const float* src = Kg + (size_t)(nt * 128) * KVD_;
        #pragma unroll
        for (int i = 0; i < 8; ++i) {
            int idx = t + i * 256;
            int n = idx >> 4, c = idx & 15;
            cpasync16(base + (unsigned)(n * KPITCH + c * 4) * 4u,
                      src + (size_t)n * KVD_ + c * 4);
        }
        asm volatile("cp.async.commit_group;\n");
    };

    float mrun[4][2], lrun[4][2];
    #pragma unroll
    for (int mi = 0; mi < 4; ++mi)
        #pragma unroll
        for (int rg = 0; rg < 2; ++rg) { mrun[mi][rg] = -1e30f; lrun[mi][rg] = 0.f; }

    prefetchK(0, 0);

    for (int nt = 0; nt < 16; ++nt) {
        if (nt < 15) {
            prefetchK(nt + 1, (nt + 1) & 1);
            asm volatile("cp.async.wait_group 1;\n");
        } else {
            asm volatile("cp.async.wait_group 0;\n");
        }
        __syncthreads();

        const float* sK = sKf + (nt & 1) * 128 * KPITCH;

        float acc[4][4][4];
        #pragma unroll
        for (int i = 0; i < 4; ++i)
            #pragma unroll
            for (int j = 0; j < 4; ++j)
                #pragma unroll
                for (int r = 0; r < 4; ++r) acc[i][j][r] = 0.f;

        #pragma unroll
        for (int ks = 0; ks < 8; ++ks) {
            const int kk  = ks * 8 + lq;
            const int kkh = kk + 4;
            unsigned a[4][4], bf[4][2];
            #pragma unroll
            for (int mi = 0; mi < 4; ++mi) {
                int r = wm * 64 + mi * 16 + lr;
                a[mi][0] = sQ[kk  * 128 + ( r      ^ sw)];
                a[mi][1] = sQ[kk  * 128 + ((r + 8) ^ sw)];
                a[mi][2] = sQ[kkh * 128 + ( r      ^ sw)];
                a[mi][3] = sQ[kkh * 128 + ((r + 8) ^ sw)];
            }
            #pragma unroll
            for (int ni = 0; ni < 4; ++ni) {
                int n = wn * 32 + ni * 8 + lr;
                bf[ni][0] = f2tf(sK[n * KPITCH + kk ]);
                bf[ni][1] = f2tf(sK[n * KPITCH + kkh]);
            }
            #pragma unroll
            for (int mi = 0; mi < 4; ++mi)
                #pragma unroll
                for (int ni = 0; ni < 4; ++ni)
                    mma_tf32(acc[mi][ni], a[mi][0], a[mi][1], a[mi][2], a[mi][3],
                             bf[ni][0], bf[ni][1]);
        }

        #pragma unroll
        for (int mi = 0; mi < 4; ++mi)
            #pragma unroll
            for (int rg = 0; rg < 2; ++rg) {
                int row = wm * 64 + mi * 16 + lr + rg * 8;
                float m8 = -1e30f;
                #pragma unroll
                for (int ni = 0; ni < 4; ++ni)
                    m8 = fmaxf(m8, fmaxf(acc[mi][ni][rg * 2], acc[mi][ni][rg * 2 + 1]));
                float l8 = 0.f;
                #pragma unroll
                for (int ni = 0; ni < 4; ++ni) {
                    int cc = wn * 32 + ni * 8 + 2 * lq;
                    float v0 = acc[mi][ni][rg * 2];
                    float v1 = acc[mi][ni][rg * 2 + 1];
                    float2 sv = { v0, v1 };
                    *(float2*)(aRow + (size_t)row * S_ + nt * 128 + cc) = sv;
                    l8 += __expf(v0 - m8) + __expf(v1 - m8);
                }
                float mn = fmaxf(mrun[mi][rg], m8);
                lrun[mi][rg] = lrun[mi][rg] * __expf(mrun[mi][rg] - mn)
                             + l8 * __expf(m8 - mn);
                mrun[mi][rg] = mn;
            }
        __syncthreads();
    }

    #pragma unroll
    for (int mi = 0; mi < 4; ++mi)
        #pragma unroll
        for (int rg = 0; rg < 2; ++rg) {
            float m = mrun[mi][rg], l = lrun[mi][rg];
            #pragma unroll
            for (int o = 1; o <= 2; o <<= 1) {
                float mo = __shfl_xor_sync(0xffffffffu, m, o);
                float lo = __shfl_xor_sync(0xffffffffu, l, o);
                float mn = fmaxf(m, mo);
                l = l * __expf(m - mn) + lo * __expf(mo - mn);
                m = mn;
            }
            if (lq == 0) {
                int row = wm * 64 + mi * 16 + lr + rg * 8;
                sRed[wn * 128 + row] = make_float2(m, l);
            }
        }
    __syncthreads();

    if (t < 128) {
        float2 p = sRed[t];
        float m = p.x, l = p.y;
        #pragma unroll
        for (int wni = 1; wni < 4; ++wni) {
            float2 q = sRed[wni * 128 + t];
            float mn = fmaxf(m, q.x);
            l = l * __expf(m - mn) + q.y * __expf(q.x - mn);
            m = mn;
        }
        stats[(size_t)bh * 2048 + mt * 128 + t] = make_float2(m, 1.0f / l);
    }
}

// ---------------------------------------------------------------------------
// Fused softmax + PV (R14 proven, register-pipelined S reads).
// ---------------------------------------------------------------------------
#define PV_SMEM_BYTES (128*132*4 + 128*64*4 + 128*8)

__global__ void __launch_bounds__(512) pv_softmax(
    const float* __restrict__ V, float* __restrict__ attn,
    const float2* __restrict__ stats, float* __restrict__ Ctx)
{
    extern __shared__ unsigned smu[];
    unsigned* sP = smu;                    // 128 x 132 (row-major P, tf32)
    unsigned* sV = sP + 128 * 132;         // 64-col k-major swizzled V
    float2* sStats = (float2*)(sV + 128 * 64);  // 128

    const int t    = threadIdx.x;
    const int w    = t >> 5;
    const int lane = t & 31;
    const int lq   = lane & 3;
    const int lr   = lane >> 2;
    const unsigned sw = lq << 3;
    const int wm2 = w & 3;
    const int wn2 = w >> 2;

    const int q0 = blockIdx.x * 128;
    const int h  = blockIdx.y;
    const int b  = blockIdx.z;
    const int hkv = h >> 2;
    const int bh  = b * HQ_ + h;

    const float* Vg = V + (size_t)b * S_ * KVD_ + hkv * D_;
    float* aBase = attn + ((size_t)bh * S_ + q0) * S_;
    float* Cg = Ctx + ((size_t)b * S_ + q0) * E_ + h * D_;

    if (t < 128) sStats[t] = stats[(size_t)bh * 2048 + q0 + t];

    // ---- S-tile register pipeline: preload tile 0 ----
    float4 vReg[8];
    #pragma unroll
    for (int i = 0; i < 8; ++i) {
        int idx = t + i * 512;
        int row = idx >> 5, c4 = idx & 31;
        vReg[i] = *(const float4*)(aBase + (size_t)row * S_ + c4 * 4);
    }
    __syncthreads();   // sStats visible

    float accO[2][2][4];
    #pragma unroll
    for (int i = 0; i < 2; ++i)
        #pragma unroll
        for (int j = 0; j < 2; ++j)
            #pragma unroll
            for (int r = 0; r < 4; ++r) accO[i][j][r] = 0.f;

    for (int kt = 0; kt < S_ / 128; ++kt) {
        // ---- stage V tile (proven swizzle) ----
        const float* Vt = Vg + (size_t)kt * 128 * KVD_;
        #pragma unroll
        for (int i = 0; i < 4; ++i) {
            int idx = t + i * 512;
            int kv = idx >> 4, q4 = idx & 15;
            float4 v = *(const float4*)(Vt + (size_t)kv * KVD_ + q4 * 4);
            unsigned c = (kv & 3) << 3;
            unsigned* dst = &sV[kv * 64 + ((q4 * 4) ^ c)];
            dst[0] = f2tf(v.x); dst[1] = f2tf(v.y);
            dst[2] = f2tf(v.z); dst[3] = f2tf(v.w);
        }

        // ---- P = exp(s-m)*inv from pipelined regs: gmem write + sP stage ----
        #pragma unroll
        for (int i = 0; i < 8; ++i) {
            int idx = t + i * 512;
            int row = idx >> 5, c4 = idx & 31;
            float2 st = sStats[row];
            float4 v = vReg[i];
            float p0 = __expf(v.x - st.x) * st.y;
            float p1 = __expf(v.y - st.x) * st.y;
            float p2 = __expf(v.z - st.x) * st.y;
            float p3 = __expf(v.w - st.x) * st.y;
            float4 pv = { p0, p1, p2, p3 };
            *(float4*)(aBase + (size_t)row * S_ + kt * 128 + c4 * 4) = pv;
            uint4 tv = { f2tf(p0), f2tf(p1), f2tf(p2), f2tf(p3) };
            *(uint4*)(&sP[row * 132 + c4 * 4]) = tv;
        }

        // ---- issue next tile's S loads (latency hides under mma phase) ----
        if (kt + 1 < S_ / 128) {
            #pragma unroll
            for (int i = 0; i < 8; ++i) {
                int idx = t + i * 512;
                int row = idx >> 5, c4 = idx & 31;
                vReg[i] = *(const float4*)(aBase + (size_t)row * S_
                                           + (kt + 1) * 128 + c4 * 4);
            }
        }
        __syncthreads();

        // ---- O += P @ V ----
        #pragma unroll
        for (int ks = 0; ks < 16; ++ks) {
            const int kk  = ks * 8 + lq;
            const int kkh = kk + 4;
            unsigned a[2][4], bf[2][2];
            #pragma unroll
            for (int mi = 0; mi < 2; ++mi) {
                int r = wm2 * 32 + mi * 16 + lr;
                a[mi][0] = sP[ r      * 132 + kk ];
                a[mi][1] = sP[(r + 8) * 132 + kk ];
                a[mi][2] = sP[ r      * 132 + kkh];
                a[mi][3] = sP[(r + 8) * 132 + kkh];
            }
            #pragma unroll
            for (int ni = 0; ni < 2; ++ni) {
                int d = wn2 * 16 + ni * 8 + lr;
                bf[ni][0] = sV[kk  * 64 + (d ^ sw)];
                bf[ni][1] = sV[kkh * 64 + (d ^ sw)];
            }
            #pragma unroll
            for (int mi = 0; mi < 2; ++mi)
                #pragma unroll
                for (int ni = 0; ni < 2; ++ni)
                    mma_tf32(accO[mi][ni], a[mi][0], a[mi][1], a[mi][2], a[mi][3],
                             bf[ni][0], bf[ni][1]);
        }
        __syncthreads();
    }

    #pragma unroll
    for (int mi = 0; mi < 2; ++mi)
        #pragma unroll
        for (int rg = 0; rg < 2; ++rg) {
            int row = wm2 * 32 + mi * 16 + lr + rg * 8;
            #pragma unroll
            for (int ni = 0; ni < 2; ++ni) {
                int d = wn2 * 16 + ni * 8 + 2 * lq;
                float2 v = { accO[mi][ni][rg * 2], accO[mi][ni][rg * 2 + 1] };
                *(float2*)(Cg + (size_t)row * E_ + d) = v;
            }
        }
}

// ---------------------------------------------------------------------------
extern "C" void kernel_launch(void* const* d_in, const int* in_sizes, int n_in,
                              void* d_out, int out_size)
{
    const float* query = (const float*)d_in[0];
    const float* key   = (const float*)d_in[1];
    const float* value = (const float*)d_in[2];
    const float* Wq = (const float*)d_in[3];
    const float* bq = (const float*)d_in[4];
    const float* Wk = (const float*)d_in[5];
    const float* bk = (const float*)d_in[6];
    const float* Wv = (const float*)d_in[7];
    const float* bv = (const float*)d_in[8];
    const float* Wo = (const float*)d_in[9];
    const float* bo = (const float*)d_in[10];
    float* out = (float*)d_out;

    float *qbuf, *kbuf, *vbuf, *cbuf;
    float2 *sbuf;
    cudaGetSymbolAddress((void**)&qbuf, g_Q);
    cudaGetSymbolAddress((void**)&kbuf, g_K);
    cudaGetSymbolAddress((void**)&vbuf, g_V);
    cudaGetSymbolAddress((void**)&cbuf, g_C);
    cudaGetSymbolAddress((void**)&sbuf, g_Stats);

    const int M = B_ * S_;                        // 4096
    float* attn = out + (size_t)B_ * S_ * E_;     // attn-weights output region

    // Projections (mm_v3: cp.async double-buffered, R10-verified numerics)
    mm_v3<<<dim3(E_/128,  M/128), 256>>>(M, E_,   E_, query, E_, Wq, E_,   qbuf, E_,   bq);
    mm_v3<<<dim3(KVD_/128, M/128), 256>>>(M, KVD_, E_, key,   E_, Wk, KVD_, kbuf, KVD_, bk);
    mm_v3<<<dim3(KVD_/128, M/128), 256>>>(M, KVD_, E_, value, E_, Wv, KVD_, vbuf, KVD_, bv);

    // Scores + exact row stats (R6 proven; clock canary ~380 us)
    cudaFuncSetAttribute(scores_v2, cudaFuncAttributeMaxDynamicSharedMemorySize,
                         SC2_SMEM_BYTES);
    scores_v2<<<dim3(16, 64), 256, SC2_SMEM_BYTES>>>(qbuf, kbuf, attn, sbuf);

    // Softmax + attn write + PV (R14 proven, register-pipelined)
    cudaFuncSetAttribute(pv_softmax, cudaFuncAttributeMaxDynamicSharedMemorySize,
                         PV_SMEM_BYTES);
    pv_softmax<<<dim3(S_/128, HQ_, B_), 512, PV_SMEM_BYTES>>>(vbuf, attn, sbuf, cbuf);

    // Output projection
    mm_v3<<<dim3(E_/128, M/128), 256>>>(M, E_, E_, cbuf, E_, Wo, E_, out, E_, bo);
}

// round 17
// speedup vs baseline: 1.5788x; 1.0433x over previous
#include <cuda_runtime.h>
#include <math.h>

// Problem constants
#define B_   2
#define S_   2048
#define E_   2048
#define HQ_  32
#define HKV_ 8
#define D_   64
#define KVD_ 512

// Scratch (static device arrays: allocation-free rule)
__device__ float  g_Q[(size_t)B_*S_*E_];       // 33.5 MB
__device__ float  g_K[(size_t)B_*S_*KVD_];     //  8.4 MB
__device__ float  g_V[(size_t)B_*S_*KVD_];     //  8.4 MB
__device__ float  g_C[(size_t)B_*S_*E_];       // 33.5 MB (context, pre-Wo)
__device__ float2 g_Stats[(size_t)64*2048];    //  1 MB  per-row (max, 1/sum)

// ---------------------------------------------------------------------------
// TF32 helpers
// ---------------------------------------------------------------------------
__device__ __forceinline__ unsigned f2tf(float f) {
    unsigned r;
    asm("cvt.rna.tf32.f32 %0, %1;" : "=r"(r) : "f"(f));
    return r;
}

__device__ __forceinline__ void mma_tf32(float c[4],
                                         unsigned a0, unsigned a1, unsigned a2, unsigned a3,
                                         unsigned b0, unsigned b1) {
    asm volatile(
        "mma.sync.aligned.m16n8k8.row.col.f32.tf32.tf32.f32 "
        "{%0,%1,%2,%3},{%4,%5,%6,%7},{%8,%9},{%0,%1,%2,%3};"
        : "+f"(c[0]), "+f"(c[1]), "+f"(c[2]), "+f"(c[3])
        : "r"(a0), "r"(a1), "r"(a2), "r"(a3), "r"(b0), "r"(b1));
}

__device__ __forceinline__ unsigned smem_u32(const void* p) {
    return (unsigned)__cvta_generic_to_shared(p);
}

__device__ __forceinline__ void cpasync16(unsigned dst, const void* src) {
    asm volatile("cp.async.ca.shared.global [%0], [%1], 16;\n" :: "r"(dst), "l"(src));
}

// ---------------------------------------------------------------------------
// Projection GEMM (R16 proven mm_v3): C = A @ B + bias. 128x128x16 tiles,
// cp.async double-buffered raw-f32 stages, tf32 convert at fragment load.
// ---------------------------------------------------------------------------
#define APITCH 20
#define BPITCH 136

__global__ void __launch_bounds__(256, 2) mm_v3(
    int M, int N, int K,
    const float* __restrict__ A, int lda,
    const float* __restrict__ Bm, int ldb,
    float* __restrict__ C, int ldc,
    const float* __restrict__ bias)
{
    __shared__ __align__(16) float sA[2][128 * APITCH];
    __shared__ __align__(16) float sB[2][16 * BPITCH];

    const int t    = threadIdx.x;
    const int w    = t >> 5;
    const int lane = t & 31;
    const int lq   = lane & 3;
    const int lr   = lane >> 2;
    const int wm   = w & 1;
    const int wn   = w >> 1;
    const int m0   = blockIdx.y * 128;
    const int n0   = blockIdx.x * 128;

    auto prefetch = [&](int k0, int buf) {
        #pragma unroll
        for (int i = 0; i < 2; ++i) {
            int idx = t + i * 256;
            int m = idx >> 2, c4 = idx & 3;
            cpasync16(smem_u32(&sA[buf][m * APITCH + c4 * 4]),
                      A + (size_t)(m0 + m) * lda + k0 + c4 * 4);
        }
        #pragma unroll
        for (int i = 0; i < 2; ++i) {
            int idx = t + i * 256;
            int k = idx >> 5, c4 = idx & 31;
            cpasync16(smem_u32(&sB[buf][k * BPITCH + c4 * 4]),
                      Bm + (size_t)(k0 + k) * ldb + n0 + c4 * 4);
        }
        asm volatile("cp.async.commit_group;\n");
    };

    float acc[4][4][4];
    #pragma unroll
    for (int i = 0; i < 4; ++i)
        #pragma unroll
        for (int j = 0; j < 4; ++j)
            #pragma unroll
            for (int r = 0; r < 4; ++r) acc[i][j][r] = 0.f;

    const int NT = K / 16;
    prefetch(0, 0);

    for (int kt = 0; kt < NT; ++kt) {
        if (kt + 1 < NT) {
            prefetch((kt + 1) * 16, (kt + 1) & 1);
            asm volatile("cp.async.wait_group 1;\n");
        } else {
            asm volatile("cp.async.wait_group 0;\n");
        }
        __syncthreads();

        const float* pA = sA[kt & 1];
        const float* pB = sB[kt & 1];

        #pragma unroll
        for (int ks = 0; ks < 2; ++ks) {
            const int kk  = ks * 8 + lq;
            const int kkh = kk + 4;
            unsigned af[4][4], bf[4][2];
            #pragma unroll
            for (int mi = 0; mi < 4; ++mi) {
                int r = wm * 64 + mi * 16 + lr;
                af[mi][0] = f2tf(pA[ r      * APITCH + kk ]);
                af[mi][1] = f2tf(pA[(r + 8) * APITCH + kk ]);
                af[mi][2] = f2tf(pA[ r      * APITCH + kkh]);
                af[mi][3] = f2tf(pA[(r + 8) * APITCH + kkh]);
            }
            #pragma unroll
            for (int ni = 0; ni < 4; ++ni) {
                int n = wn * 32 + ni * 8 + lr;
                bf[ni][0] = f2tf(pB[kk  * BPITCH + n]);
                bf[ni][1] = f2tf(pB[kkh * BPITCH + n]);
            }
            #pragma unroll
            for (int mi = 0; mi < 4; ++mi)
                #pragma unroll
                for (int ni = 0; ni < 4; ++ni)
                    mma_tf32(acc[mi][ni], af[mi][0], af[mi][1], af[mi][2], af[mi][3],
                             bf[ni][0], bf[ni][1]);
        }
        __syncthreads();
    }

    #pragma unroll
    for (int mi = 0; mi < 4; ++mi) {
        int r0 = m0 + wm * 64 + mi * 16 + lr;
        int r1 = r0 + 8;
        #pragma unroll
        for (int ni = 0; ni < 4; ++ni) {
            int cc = n0 + wn * 32 + ni * 8 + 2 * lq;
            float b0 = bias[cc], b1 = bias[cc + 1];
            float2 v0 = { acc[mi][ni][0] + b0, acc[mi][ni][1] + b1 };
            float2 v1 = { acc[mi][ni][2] + b0, acc[mi][ni][3] + b1 };
            *(float2*)(C + (size_t)r0 * ldc + cc) = v0;
            *(float2*)(C + (size_t)r1 * ldc + cc) = v1;
        }
    }
}

// ---------------------------------------------------------------------------
// Scores kernel (R6 proven; clock canary ~380 us): persistent Q, cp.async
// double-buffered K. Raw S -> attn buffer; per-row (max, 1/sum) -> g_Stats.
// ---------------------------------------------------------------------------
#define KPITCH 68
#define SC2_SMEM_BYTES (8192*4 + 2*128*KPITCH*4 + 4*128*8)

__global__ void __launch_bounds__(256, 2) scores_v2(
    const float* __restrict__ Q, const float* __restrict__ K,
    float* __restrict__ attn, float2* __restrict__ stats)
{
    extern __shared__ unsigned smu[];
    unsigned* sQ   = smu;                        // 64x128 tf32 (k-major swz)
    float*    sKf  = (float*)(sQ + 8192);        // 2 x 128 x 68 raw f32
    float2*   sRed = (float2*)(sKf + 2 * 128 * KPITCH);

    const int t    = threadIdx.x;
    const int w    = t >> 5;
    const int lane = t & 31;
    const int lq   = lane & 3;
    const int lr   = lane >> 2;
    const unsigned sw = lq << 3;
    const int wm = w & 1;
    const int wn = w >> 1;

    const int mt = blockIdx.x;
    const int bh = blockIdx.y;
    const int b  = bh >> 5;
    const int h  = bh & 31;
    const int hkv = h >> 2;

    const float* Qg = Q + ((size_t)b * S_ + mt * 128) * E_ + h * D_;
    const float* Kg = K + (size_t)b * S_ * KVD_ + hkv * D_;
    float* aRow = attn + (size_t)bh * S_ * S_ + (size_t)(mt * 128) * S_;

    #pragma unroll
    for (int i = 0; i < 8; ++i) {
        int idx = t + i * 256;
        int m = idx >> 4, q4 = idx & 15;
        float4 v = *(const float4*)(Qg + (size_t)m * E_ + q4 * 4);
        int kb = q4 * 4;
        sQ[(kb + 0) * 128 + (m ^ 0 )] = f2tf(0.125f * v.x);
        sQ[(kb + 1) * 128 + (m ^ 8 )] = f2tf(0.125f * v.y);
        sQ[(kb + 2) * 128 + (m ^ 16)] = f2tf(0.125f * v.z);
        sQ[(kb + 3) * 128 + (m ^ 24)] = f2tf(0.125f * v.w);
    }

    auto prefetchK = [&](int nt, int buf) {
        unsigned base = smem_u32(sKf + buf * 128 * KPITCH);
        const float* src = Kg + (size_t)(nt * 128) * KVD_;
        #pragma unroll
        for (int i = 0; i < 8; ++i) {
            int idx = t + i * 256;
            int n = idx >> 4, c = idx & 15;
            cpasync16(base + (unsigned)(n * KPITCH + c * 4) * 4u,
                      src + (size_t)n * KVD_ + c * 4);
        }
        asm volatile("cp.async.commit_group;\n");
    };

    float mrun[4][2], lrun[4][2];
    #pragma unroll
    for (int mi = 0; mi < 4; ++mi)
        #pragma unroll
        for (int rg = 0; rg < 2; ++rg) { mrun[mi][rg] = -1e30f; lrun[mi][rg] = 0.f; }

    prefetchK(0, 0);

    for (int nt = 0; nt < 16; ++nt) {
        if (nt < 15) {
            prefetchK(nt + 1, (nt + 1) & 1);
            asm volatile("cp.async.wait_group 1;\n");
        } else {
            asm volatile("cp.async.wait_group 0;\n");
        }
        __syncthreads();

        const float* sK = sKf + (nt & 1) * 128 * KPITCH;

        float acc[4][4][4];
        #pragma unroll
        for (int i = 0; i < 4; ++i)
            #pragma unroll
            for (int j = 0; j < 4; ++j)
                #pragma unroll
                for (int r = 0; r < 4; ++r) acc[i][j][r] = 0.f;

        #pragma unroll
        for (int ks = 0; ks < 8; ++ks) {
            const int kk  = ks * 8 + lq;
            const int kkh = kk + 4;
            unsigned a[4][4], bf[4][2];
            #pragma unroll
            for (int mi = 0; mi < 4; ++mi) {
                int r = wm * 64 + mi * 16 + lr;
                a[mi][0] = sQ[kk  * 128 + ( r      ^ sw)];
                a[mi][1] = sQ[kk  * 128 + ((r + 8) ^ sw)];
                a[mi][2] = sQ[kkh * 128 + ( r      ^ sw)];
                a[mi][3] = sQ[kkh * 128 + ((r + 8) ^ sw)];
            }
            #pragma unroll
            for (int ni = 0; ni < 4; ++ni) {
                int n = wn * 32 + ni * 8 + lr;
                bf[ni][0] = f2tf(sK[n * KPITCH + kk ]);
                bf[ni][1] = f2tf(sK[n * KPITCH + kkh]);
            }
            #pragma unroll
            for (int mi = 0; mi < 4; ++mi)
                #pragma unroll
                for (int ni = 0; ni < 4; ++ni)
                    mma_tf32(acc[mi][ni], a[mi][0], a[mi][1], a[mi][2], a[mi][3],
                             bf[ni][0], bf[ni][1]);
        }

        #pragma unroll
        for (int mi = 0; mi < 4; ++mi)
            #pragma unroll
            for (int rg = 0; rg < 2; ++rg) {
                int row = wm * 64 + mi * 16 + lr + rg * 8;
                float m8 = -1e30f;
                #pragma unroll
                for (int ni = 0; ni < 4; ++ni)
                    m8 = fmaxf(m8, fmaxf(acc[mi][ni][rg * 2], acc[mi][ni][rg * 2 + 1]));
                float l8 = 0.f;
                #pragma unroll
                for (int ni = 0; ni < 4; ++ni) {
                    int cc = wn * 32 + ni * 8 + 2 * lq;
                    float v0 = acc[mi][ni][rg * 2];
                    float v1 = acc[mi][ni][rg * 2 + 1];
                    float2 sv = { v0, v1 };
                    *(float2*)(aRow + (size_t)row * S_ + nt * 128 + cc) = sv;
                    l8 += __expf(v0 - m8) + __expf(v1 - m8);
                }
                float mn = fmaxf(mrun[mi][rg], m8);
                lrun[mi][rg] = lrun[mi][rg] * __expf(mrun[mi][rg] - mn)
                             + l8 * __expf(m8 - mn);
                mrun[mi][rg] = mn;
            }
        __syncthreads();
    }

    #pragma unroll
    for (int mi = 0; mi < 4; ++mi)
        #pragma unroll
        for (int rg = 0; rg < 2; ++rg) {
            float m = mrun[mi][rg], l = lrun[mi][rg];
            #pragma unroll
            for (int o = 1; o <= 2; o <<= 1) {
                float mo = __shfl_xor_sync(0xffffffffu, m, o);
                float lo = __shfl_xor_sync(0xffffffffu, l, o);
                float mn = fmaxf(m, mo);
                l = l * __expf(m - mn) + lo * __expf(mo - mn);
                m = mn;
            }
            if (lq == 0) {
                int row = wm * 64 + mi * 16 + lr + rg * 8;
                sRed[wn * 128 + row] = make_float2(m, l);
            }
        }
    __syncthreads();

    if (t < 128) {
        float2 p = sRed[t];
        float m = p.x, l = p.y;
        #pragma unroll
        for (int wni = 1; wni < 4; ++wni) {
            float2 q = sRed[wni * 128 + t];
            float mn = fmaxf(m, q.x);
            l = l * __expf(m - mn) + q.y * __expf(q.x - mn);
            m = mn;
        }
        stats[(size_t)bh * 2048 + mt * 128 + t] = make_float2(m, 1.0f / l);
    }
}

// ---------------------------------------------------------------------------
// Fused softmax + PV, v3: R14's register-pipelined S reads, plus V staged
// via cp.async into raw f32 pitch-72 rows (72 mod 32 = 8 -> fragment-load
// bank = 8*lq + lr, all 32 distinct -> conflict-free), f2tf at fragment
// load. Removes 8192 scalar STS + staging f2tf + V LDG latency per tile.
// ---------------------------------------------------------------------------
#define VPITCH 72
#define PV_SMEM_BYTES (128*132*4 + 128*VPITCH*4 + 128*8)

__global__ void __launch_bounds__(512) pv_softmax(
    const float* __restrict__ V, float* __restrict__ attn,
    const float2* __restrict__ stats, float* __restrict__ Ctx)
{
    extern __shared__ unsigned smu[];
    unsigned* sP  = smu;                    // 128 x 132 (row-major P, tf32)
    float*   sVf  = (float*)(sP + 128 * 132);  // 128 x 72 raw f32 V
    float2* sStats = (float2*)(sVf + 128 * VPITCH);  // 128

    const int t    = threadIdx.x;
    const int w    = t >> 5;
    const int lane = t & 31;
    const int lq   = lane & 3;
    const int lr   = lane >> 2;
    const int wm2  = w & 3;
    const int wn2  = w >> 2;

    const int q0 = blockIdx.x * 128;
    const int h  = blockIdx.y;
    const int b  = blockIdx.z;
    const int hkv = h >> 2;
    const int bh  = b * HQ_ + h;

    const float* Vg = V + (size_t)b * S_ * KVD_ + hkv * D_;
    float* aBase = attn + ((size_t)bh * S_ + q0) * S_;
    float* Cg = Ctx + ((size_t)b * S_ + q0) * E_ + h * D_;

    if (t < 128) sStats[t] = stats[(size_t)bh * 2048 + q0 + t];

    // ---- S-tile register pipeline: preload tile 0 ----
    float4 vReg[8];
    #pragma unroll
    for (int i = 0; i < 8; ++i) {
        int idx = t + i * 512;
        int row = idx >> 5, c4 = idx & 31;
        vReg[i] = *(const float4*)(aBase + (size_t)row * S_ + c4 * 4);
    }
    __syncthreads();   // sStats visible

    float accO[2][2][4];
    #pragma unroll
    for (int i = 0; i < 2; ++i)
        #pragma unroll
        for (int j = 0; j < 2; ++j)
            #pragma unroll
            for (int r = 0; r < 4; ++r) accO[i][j][r] = 0.f;

    for (int kt = 0; kt < S_ / 128; ++kt) {
        // ---- issue V tile cp.async (raw f32, pitch 72) ----
        {
            const float* Vt = Vg + (size_t)kt * 128 * KVD_;
            #pragma unroll
            for (int i = 0; i < 4; ++i) {
                int idx = t + i * 512;
                int kv = idx >> 4, c = idx & 15;
                cpasync16(smem_u32(sVf + kv * VPITCH + c * 4),
                          Vt + (size_t)kv * KVD_ + c * 4);
            }
            asm volatile("cp.async.commit_group;\n");
        }

        // ---- P = exp(s-m)*inv from pipelined regs: gmem write + sP stage ----
        #pragma unroll
        for (int i = 0; i < 8; ++i) {
            int idx = t + i * 512;
            int row = idx >> 5, c4 = idx & 31;
            float2 st = sStats[row];
            float4 v = vReg[i];
            float p0 = __expf(v.x - st.x) * st.y;
            float p1 = __expf(v.y - st.x) * st.y;
            float p2 = __expf(v.z - st.x) * st.y;
            float p3 = __expf(v.w - st.x) * st.y;
            float4 pv = { p0, p1, p2, p3 };
            *(float4*)(aBase + (size_t)row * S_ + kt * 128 + c4 * 4) = pv;
            uint4 tv = { f2tf(p0), f2tf(p1), f2tf(p2), f2tf(p3) };
            *(uint4*)(&sP[row * 132 + c4 * 4]) = tv;
        }

        // ---- issue next tile's S loads (latency hides under mma phase) ----
        if (kt + 1 < S_ / 128) {
            #pragma unroll
            for (int i = 0; i < 8; ++i) {
                int idx = t + i * 512;
                int row = idx >> 5, c4 = idx & 31;
                vReg[i] = *(const float4*)(aBase + (size_t)row * S_
                                           + (kt + 1) * 128 + c4 * 4);
            }
        }
        asm volatile("cp.async.wait_group 0;\n");
        __syncthreads();

        // ---- O += P @ V ----
        #pragma unroll
        for (int ks = 0; ks < 16; ++ks) {
            const int kk  = ks * 8 + lq;
            const int kkh = kk + 4;
            unsigned a[2][4], bf[2][2];
            #pragma unroll
            for (int mi = 0; mi < 2; ++mi) {
                int r = wm2 * 32 + mi * 16 + lr;
                a[mi][0] = sP[ r      * 132 + kk ];
                a[mi][1] = sP[(r + 8) * 132 + kk ];
                a[mi][2] = sP[ r      * 132 + kkh];
                a[mi][3] = sP[(r + 8) * 132 + kkh];
            }
            #pragma unroll
            for (int ni = 0; ni < 2; ++ni) {
                int d = wn2 * 16 + ni * 8 + lr;
                bf[ni][0] = f2tf(sVf[kk  * VPITCH + d]);
                bf[ni][1] = f2tf(sVf[kkh * VPITCH + d]);
            }
            #pragma unroll
            for (int mi = 0; mi < 2; ++mi)
                #pragma unroll
                for (int ni = 0; ni < 2; ++ni)
                    mma_tf32(accO[mi][ni], a[mi][0], a[mi][1], a[mi][2], a[mi][3],
                             bf[ni][0], bf[ni][1]);
        }
        __syncthreads();
    }

    #pragma unroll
    for (int mi = 0; mi < 2; ++mi)
        #pragma unroll
        for (int rg = 0; rg < 2; ++rg) {
            int row = wm2 * 32 + mi * 16 + lr + rg * 8;
            #pragma unroll
            for (int ni = 0; ni < 2; ++ni) {
                int d = wn2 * 16 + ni * 8 + 2 * lq;
                float2 v = { accO[mi][ni][rg * 2], accO[mi][ni][rg * 2 + 1] };
                *(float2*)(Cg + (size_t)row * E_ + d) = v;
            }
        }
}

// ---------------------------------------------------------------------------
extern "C" void kernel_launch(void* const* d_in, const int* in_sizes, int n_in,
                              void* d_out, int out_size)
{
    const float* query = (const float*)d_in[0];
    const float* key   = (const float*)d_in[1];
    const float* value = (const float*)d_in[2];
    const float* Wq = (const float*)d_in[3];
    const float* bq = (const float*)d_in[4];
    const float* Wk = (const float*)d_in[5];
    const float* bk = (const float*)d_in[6];
    const float* Wv = (const float*)d_in[7];
    const float* bv = (const float*)d_in[8];
    const float* Wo = (const float*)d_in[9];
    const float* bo = (const float*)d_in[10];
    float* out = (float*)d_out;

    float *qbuf, *kbuf, *vbuf, *cbuf;
    float2 *sbuf;
    cudaGetSymbolAddress((void**)&qbuf, g_Q);
    cudaGetSymbolAddress((void**)&kbuf, g_K);
    cudaGetSymbolAddress((void**)&vbuf, g_V);
    cudaGetSymbolAddress((void**)&cbuf, g_C);
    cudaGetSymbolAddress((void**)&sbuf, g_Stats);

    const int M = B_ * S_;                        // 4096
    float* attn = out + (size_t)B_ * S_ * E_;     // attn-weights output region

    // Projections (mm_v3, R16 proven)
    mm_v3<<<dim3(E_/128,  M/128), 256>>>(M, E_,   E_, query, E_, Wq, E_,   qbuf, E_,   bq);
    mm_v3<<<dim3(KVD_/128, M/128), 256>>>(M, KVD_, E_, key,   E_, Wk, KVD_, kbuf, KVD_, bk);
    mm_v3<<<dim3(KVD_/128, M/128), 256>>>(M, KVD_, E_, value, E_, Wv, KVD_, vbuf, KVD_, bv);

    // Scores + exact row stats (R6 proven; clock canary ~380 us)
    cudaFuncSetAttribute(scores_v2, cudaFuncAttributeMaxDynamicSharedMemorySize,
                         SC2_SMEM_BYTES);
    scores_v2<<<dim3(16, 64), 256, SC2_SMEM_BYTES>>>(qbuf, kbuf, attn, sbuf);

    // Softmax + attn write + PV (v3: cp.async V path)
    cudaFuncSetAttribute(pv_softmax, cudaFuncAttributeMaxDynamicSharedMemorySize,
                         PV_SMEM_BYTES);
    pv_softmax<<<dim3(S_/128, HQ_, B_), 512, PV_SMEM_BYTES>>>(vbuf, attn, sbuf, cbuf);

    // Output projection
    mm_v3<<<dim3(E_/128, M/128), 256>>>(M, E_, E_, cbuf, E_, Wo, E_, out, E_, bo);
}